// round 5
// baseline (speedup 1.0000x reference)
#include <cuda_runtime.h>
#include <cuda_bf16.h>
#include <cstdint>

#define NN 20000
#define EE 160000
#define GG 64
#define MAXD 512
#define WTOT 688128

// ---------------- scratch (interleaved bf16 hi/lo planes) -------------------
// Layout per row: granule-pairs of [16B hi (8 elems) | 16B lo (8 elems)] along K.
__device__ __align__(16) unsigned short g_x[NN * 256];        // K=128
__device__ __align__(16) unsigned short g_ag[NN * MAXD * 2];
__device__ __align__(16) unsigned short g_pA[NN * MAXD * 2];
__device__ __align__(16) unsigned short g_pB[NN * MAXD * 2];
__device__ __align__(16) unsigned short g_wl[WTOT * 2];
__device__ __align__(16) unsigned short g_wr[WTOT * 2];
__device__ int   g_rowptr[NN + 1];
__device__ int   g_fill[NN];
__device__ int   g_csr[EE];
__device__ float g_pool[GG * 256];
__device__ int   g_gs[GG];
__device__ int   g_ge[GG];

__constant__ int c_din[6]  = {128, 256, 256, 512, 512, 256};
__constant__ int c_dout[6] = {256, 256, 512, 512, 256, 256};
__constant__ int c_woff[6] = {0, 32768, 98304, 229376, 491520, 622592};

struct WPtrs { const float* w[12]; };

// ---------------- helpers ----------------------------------------------------
__device__ __forceinline__ uint32_t smem_u32(const void* p) {
    uint32_t a;
    asm("{ .reg .u64 t; cvta.to.shared.u64 t, %1; cvt.u32.u64 %0, t; }" : "=r"(a) : "l"(p));
    return a;
}
__device__ __forceinline__ uint32_t pk2(float a, float b) {  // low16=a, high16=b
    uint32_t r;
    asm("cvt.rn.bf16x2.f32 %0, %1, %2;" : "=r"(r) : "f"(b), "f"(a));
    return r;
}
__device__ __forceinline__ void split2(float v0, float v1, uint32_t& hp, uint32_t& lp) {
    hp = pk2(v0, v1);
    float h0 = __uint_as_float(hp << 16);
    float h1 = __uint_as_float(hp & 0xFFFF0000u);
    lp = pk2(v0 - h0, v1 - h1);
}
__device__ __forceinline__ void ldm4(uint32_t* r, uint32_t a) {
    asm volatile("ldmatrix.sync.aligned.m8n8.x4.shared.b16 {%0,%1,%2,%3}, [%4];"
                 : "=r"(r[0]), "=r"(r[1]), "=r"(r[2]), "=r"(r[3]) : "r"(a));
}
#define MMA_BF16(c, a, b)                                                          \
    asm volatile("mma.sync.aligned.m16n8k16.row.col.f32.bf16.bf16.f32 "            \
        "{%0,%1,%2,%3}, {%4,%5,%6,%7}, {%8,%9}, {%0,%1,%2,%3};"                     \
        : "+f"((c)[0]), "+f"((c)[1]), "+f"((c)[2]), "+f"((c)[3])                    \
        : "r"((a)[0]), "r"((a)[1]), "r"((a)[2]), "r"((a)[3]),                       \
          "r"((b)[0]), "r"((b)[1]))
#define CP16(dst, src, sz)                                                         \
    asm volatile("cp.async.cg.shared.global [%0], [%1], 16, %2;"                    \
        :: "r"(dst), "l"(src), "r"(sz) : "memory")
#define CP_COMMIT() asm volatile("cp.async.commit_group;" ::: "memory")
#define CP_WAIT1()  asm volatile("cp.async.wait_group 1;" ::: "memory")

// ---------------- fused convert: x split + weight transpose/split -----------
__global__ void k_cvtall(const float* __restrict__ x, WPtrs wp) {
    int t = threadIdx.x;
    if (blockIdx.y == 0) {
        int gi = blockIdx.x * 256 + t;  // one granule-pair (8 elems)
        if (gi < NN * 16) {
            const float4* xs = (const float4*)(x + (size_t)gi * 8);
            float4 v0 = xs[0], v1 = xs[1];
            uint32_t h0, l0, h1, l1, h2, l2, h3, l3;
            split2(v0.x, v0.y, h0, l0); split2(v0.z, v0.w, h1, l1);
            split2(v1.x, v1.y, h2, l2); split2(v1.z, v1.w, h3, l3);
            uint4* dst = (uint4*)g_x + (size_t)gi * 2;
            dst[0] = make_uint4(h0, h1, h2, h3);
            dst[1] = make_uint4(l0, l1, l2, l3);
        }
    } else {
        int id = blockIdx.y - 1, li = id >> 1, lr = id & 1;
        int K = c_din[li], Ncol = c_dout[li];
        int i = blockIdx.x * 256 + t;
        if (i < K * Ncol) {
            int k = i / Ncol, n = i % Ncol;
            const float* W = wp.w[id];
            float v = W[i];
            uint32_t hp = pk2(v, v);
            float hf = __uint_as_float(hp << 16);
            uint32_t lp = pk2(v - hf, 0.f);
            unsigned short* dst = (lr ? g_wr : g_wl) + (size_t)c_woff[li] * 2;
            size_t o = (size_t)n * K * 2 + (size_t)(k >> 3) * 16 + (k & 7);
            dst[o]     = (unsigned short)(hp & 0xFFFFu);
            dst[o + 8] = (unsigned short)(lp & 0xFFFFu);
        }
    }
}

// ---------------- fused CSR count + scan (single block) ---------------------
__global__ void k_csr(const int* __restrict__ ei) {
    extern __shared__ int sdeg[];
    __shared__ int part[1024];
    int t = threadIdx.x;
    for (int i = t; i < NN; i += 1024) sdeg[i] = 0;
    if (t < GG) { g_gs[t] = NN; g_ge[t] = 0; }
    __syncthreads();
    for (int e = t; e < EE; e += 1024) atomicAdd(&sdeg[ei[EE + e]], 1);
    __syncthreads();
    const int CH = (NN + 1023) / 1024;
    int base = t * CH, s = 0;
    for (int i = 0; i < CH; i++) { int idx = base + i; if (idx < NN) s += sdeg[idx]; }
    part[t] = s;
    __syncthreads();
    for (int off = 1; off < 1024; off <<= 1) {
        int v = (t >= off) ? part[t - off] : 0;
        __syncthreads(); part[t] += v; __syncthreads();
    }
    int run = (t == 0) ? 0 : part[t - 1];
    for (int i = 0; i < CH; i++) {
        int idx = base + i;
        if (idx < NN) { int c = sdeg[idx]; g_rowptr[idx] = run; g_fill[idx] = run; run += c; }
    }
    if (t == 1023) g_rowptr[NN] = part[1023];
}
__global__ void k_fillcsr(const int* __restrict__ ei) {
    int e = blockIdx.x * blockDim.x + threadIdx.x;
    if (e < EE) { int d = ei[EE + e]; int p = atomicAdd(&g_fill[d], 1); g_csr[p] = ei[e]; }
}

// ---------------- mean aggregation (warp/node, interleaved planes) ----------
__global__ void k_agg(const unsigned short* __restrict__ in,
                      unsigned short* __restrict__ out, int K) {
    int node = blockIdx.x * 8 + (threadIdx.x >> 5);
    if (node >= NN) return;
    int lane = threadIdx.x & 31;
    int beg = g_rowptr[node], end = g_rowptr[node + 1];
    int passes = K >> 7;  // uint4 loads per lane per row (1,2,2,4)
    float acc[4][8];
#pragma unroll
    for (int p = 0; p < 4; p++)
#pragma unroll
        for (int j = 0; j < 8; j++) acc[p][j] = 0.f;
    for (int e = beg; e < end; e++) {
        const uint4* row = (const uint4*)(in + (size_t)g_csr[e] * K * 2);
        for (int p = 0; p < passes; p++) {
            uint4 v = row[lane + (p << 5)];
            acc[p][0] += __uint_as_float(v.x << 16);
            acc[p][1] += __uint_as_float(v.x & 0xFFFF0000u);
            acc[p][2] += __uint_as_float(v.y << 16);
            acc[p][3] += __uint_as_float(v.y & 0xFFFF0000u);
            acc[p][4] += __uint_as_float(v.z << 16);
            acc[p][5] += __uint_as_float(v.z & 0xFFFF0000u);
            acc[p][6] += __uint_as_float(v.w << 16);
            acc[p][7] += __uint_as_float(v.w & 0xFFFF0000u);
        }
    }
    int d = end - beg;
    float inv = 1.0f / (float)(d > 0 ? d : 1);
    uint4* orow = (uint4*)(out + (size_t)node * K * 2);
    bool isLo = lane & 1;
    for (int p = 0; p < passes; p++) {
        float m[8];
#pragma unroll
        for (int j = 0; j < 8; j++)
            m[j] = (acc[p][j] + __shfl_xor_sync(0xFFFFFFFFu, acc[p][j], 1)) * inv;
        uint32_t u[4];
#pragma unroll
        for (int j = 0; j < 4; j++) {
            uint32_t hp, lp;
            split2(m[2 * j], m[2 * j + 1], hp, lp);
            u[j] = isLo ? lp : hp;
        }
        orow[lane + (p << 5)] = make_uint4(u[0], u[1], u[2], u[3]);
    }
}

// ---------------- bf16 3x-split dual GEMM, 3-stage cp.async -----------------
#define T_A 0
#define T_B 16384
#define STAGE_B 32768
#define SMEM_BYTES 98304

template <bool LEAKY>
__global__ void __launch_bounds__(256, 2) k_gemm_tc(
    const unsigned short* __restrict__ A1, const unsigned short* __restrict__ A2,
    const unsigned short* __restrict__ W1, const unsigned short* __restrict__ W2,
    const float* __restrict__ bias, unsigned short* __restrict__ O,
    int K, int DOUT)
{
    extern __shared__ char smem[];
    const uint32_t sb = smem_u32(smem);
    const int t = threadIdx.x, lane = t & 31, wid = t >> 5;
    const int wr = wid >> 2, wc = wid & 3;
    const int m0 = blockIdx.y * 128, n0 = blockIdx.x * 128;
    const int nc = K / 32, tot = 2 * nc;

    float acc[4][4][4];
#pragma unroll
    for (int i = 0; i < 4; i++)
#pragma unroll
        for (int j = 0; j < 4; j++)
#pragma unroll
            for (int k = 0; k < 4; k++) acc[i][j][k] = 0.f;

    // fill constants: thread -> (row = t>>1, granules gsel..gsel+3)
    const int frow = t >> 1;
    const uint32_t gsel = (uint32_t)(t & 1) * 4;
    const uint32_t rowb = (uint32_t)frow * 128;
    const uint32_t fswz = (uint32_t)(frow & 7) << 4;
    const int gra = m0 + frow;
    const uint32_t szA = (gra < NN) ? 16u : 0u;
    const size_t aoff = (size_t)(gra < NN ? gra : NN - 1) * K * 4;
    const size_t boff = (size_t)(n0 + frow) * K * 4;

    // MMA address constants
    const uint32_t lswz = (uint32_t)(lane & 7) << 4;
    const uint32_t arow = (uint32_t)(wr * 64 + (lane & 7) + ((lane >> 3) & 1) * 8);
    const uint32_t agr  = ((uint32_t)(lane >> 4)) * 32;
    const uint32_t brow = (uint32_t)(wc * 32 + (lane >> 4) * 8 + (lane & 7));
    const uint32_t bgr  = ((uint32_t)((lane >> 3) & 1)) * 32;

#define FILL(ch, stg) do {                                                         \
    const unsigned short *as_, *bs_; int kb_;                                      \
    if ((ch) < nc) { as_ = A1; bs_ = W1; kb_ = (ch) * 32; }                         \
    else           { as_ = A2; bs_ = W2; kb_ = ((ch) - nc) * 32; }                  \
    uint32_t sd_ = sb + (uint32_t)(stg) * STAGE_B + rowb;                           \
    const char* asrc = (const char*)as_ + aoff + (size_t)kb_ * 4;                   \
    const char* bsrc = (const char*)bs_ + boff + (size_t)kb_ * 4;                   \
    _Pragma("unroll")                                                               \
    for (int i_ = 0; i_ < 4; i_++) {                                                \
        uint32_t g_ = gsel + i_;                                                    \
        uint32_t off_ = (g_ * 16) ^ fswz;                                           \
        CP16(sd_ + T_A + off_, asrc + g_ * 16, szA);                                \
        CP16(sd_ + T_B + off_, bsrc + g_ * 16, 16u);                                \
    }                                                                               \
    CP_COMMIT();                                                                    \
} while (0)

    FILL(0, 0);
    FILL(1, 1);

    int stg = 0;
    for (int ch = 0; ch < tot; ch++) {
        CP_WAIT1();
        __syncthreads();
        if (ch + 2 < tot) {
            int ns = stg + 2; if (ns >= 3) ns -= 3;
            FILL(ch + 2, ns);
        } else {
            CP_COMMIT();
        }
        const uint32_t s0 = sb + (uint32_t)stg * STAGE_B;
#pragma unroll
        for (int ks = 0; ks < 2; ks++) {
            const uint32_t colb = (uint32_t)ks * 64;
            uint32_t bh[4][2], bl[4][2];
#pragma unroll
            for (int ntp = 0; ntp < 2; ntp++) {
                uint32_t rb_ = s0 + T_B + (brow + (uint32_t)ntp * 16) * 128;
                uint32_t rg[4];
                ldm4(rg, rb_ + ((colb + bgr) ^ lswz));
                bh[2 * ntp][0] = rg[0]; bh[2 * ntp][1] = rg[1];
                bh[2 * ntp + 1][0] = rg[2]; bh[2 * ntp + 1][1] = rg[3];
                ldm4(rg, rb_ + ((colb + 16 + bgr) ^ lswz));
                bl[2 * ntp][0] = rg[0]; bl[2 * ntp][1] = rg[1];
                bl[2 * ntp + 1][0] = rg[2]; bl[2 * ntp + 1][1] = rg[3];
            }
#pragma unroll
            for (int mt = 0; mt < 4; mt++) {
                uint32_t ab_ = s0 + T_A + (arow + (uint32_t)mt * 16) * 128;
                uint32_t ah[4], al[4];
                ldm4(ah, ab_ + ((colb + agr) ^ lswz));
                ldm4(al, ab_ + ((colb + 16 + agr) ^ lswz));
#pragma unroll
                for (int nt = 0; nt < 4; nt++) {
                    MMA_BF16(acc[mt][nt], ah, bh[nt]);
                    MMA_BF16(acc[mt][nt], ah, bl[nt]);
                    MMA_BF16(acc[mt][nt], al, bh[nt]);
                }
            }
        }
        stg++; if (stg >= 3) stg = 0;
    }
#undef FILL

    // epilogue: bias + optional leaky; interleaved hi/lo out
#pragma unroll
    for (int mt = 0; mt < 4; mt++) {
        int r0 = m0 + wr * 64 + mt * 16 + (lane >> 2);
        int r1 = r0 + 8;
#pragma unroll
        for (int nt = 0; nt < 4; nt++) {
            int c0 = n0 + wc * 32 + nt * 8 + (lane & 3) * 2;
            float2 b2 = *(const float2*)(bias + c0);
            float v0 = acc[mt][nt][0] + b2.x;
            float v1 = acc[mt][nt][1] + b2.y;
            float v2 = acc[mt][nt][2] + b2.x;
            float v3 = acc[mt][nt][3] + b2.y;
            if (LEAKY) {
                v0 = v0 >= 0.f ? v0 : 0.01f * v0;
                v1 = v1 >= 0.f ? v1 : 0.01f * v1;
                v2 = v2 >= 0.f ? v2 : 0.01f * v2;
                v3 = v3 >= 0.f ? v3 : 0.01f * v3;
            }
            size_t cb = (size_t)((c0 >> 3) * 32 + (c0 & 7) * 2);
            uint32_t hp, lp;
            if (r0 < NN) {
                char* p = (char*)O + (size_t)r0 * DOUT * 4 + cb;
                split2(v0, v1, hp, lp);
                *(uint32_t*)p = hp;
                *(uint32_t*)(p + 16) = lp;
            }
            if (r1 < NN) {
                char* p = (char*)O + (size_t)r1 * DOUT * 4 + cb;
                split2(v2, v3, hp, lp);
                *(uint32_t*)p = hp;
                *(uint32_t*)(p + 16) = lp;
            }
        }
    }
}

// ---------------- pool + head ------------------------------------------------
__global__ void k_bounds(const int* __restrict__ batch) {
    int n = blockIdx.x * blockDim.x + threadIdx.x;
    if (n < NN) {
        int b = batch[n];
        atomicMin(&g_gs[b], n);
        atomicMax(&g_ge[b], n + 1);
    }
}
__global__ void k_pool(const unsigned short* __restrict__ H) {
    int g = blockIdx.x, f = threadIdx.x;
    int s = g_gs[g], e = g_ge[g];
    size_t off = (size_t)(f >> 3) * 16 + (f & 7);
    float sum = 0.f;
    for (int n = s; n < e; n++) {
        const unsigned short* row = H + (size_t)n * 512;
        sum += __uint_as_float(((uint32_t)row[off]) << 16)
             + __uint_as_float(((uint32_t)row[off + 8]) << 16);
    }
    int c = e - s; if (c < 1) c = 1;
    g_pool[g * 256 + f] = sum / (float)c;
}
__global__ void k_final(const float* __restrict__ Wlin, const float* __restrict__ blin,
                        float* __restrict__ out) {
    int idx = threadIdx.x;
    if (idx >= GG * 6) return;
    int g = idx / 6, o = idx % 6;
    float s = blin[o];
#pragma unroll 8
    for (int k = 0; k < 256; k++) s += g_pool[g * 256 + k] * Wlin[k * 6 + o];
    out[idx] = s;
}

// ---------------- launcher ----------------------------------------------------
extern "C" void kernel_launch(void* const* d_in, const int* in_sizes, int n_in,
                              void* d_out, int out_size) {
    const float* x     = (const float*)d_in[0];
    const int*   ei    = (const int*)d_in[1];
    const int*   batch = (const int*)d_in[2];
    WPtrs wp;
    const float* blp[6];
    for (int l = 0; l < 6; l++) {
        wp.w[2 * l]     = (const float*)d_in[3 + 3 * l];  // Wl
        blp[l]          = (const float*)d_in[4 + 3 * l];
        wp.w[2 * l + 1] = (const float*)d_in[5 + 3 * l];  // Wr
    }
    const float* Wlin = (const float*)d_in[21];
    const float* blin = (const float*)d_in[22];
    float* out = (float*)d_out;

    unsigned short *xb, *ag, *pA, *pB, *wl, *wr;
    cudaGetSymbolAddress((void**)&xb, g_x);
    cudaGetSymbolAddress((void**)&ag, g_ag);
    cudaGetSymbolAddress((void**)&pA, g_pA);
    cudaGetSymbolAddress((void**)&pB, g_pB);
    cudaGetSymbolAddress((void**)&wl, g_wl);
    cudaGetSymbolAddress((void**)&wr, g_wr);

    cudaFuncSetAttribute(k_gemm_tc<true>,  cudaFuncAttributeMaxDynamicSharedMemorySize, SMEM_BYTES);
    cudaFuncSetAttribute(k_gemm_tc<false>, cudaFuncAttributeMaxDynamicSharedMemorySize, SMEM_BYTES);
    cudaFuncSetAttribute(k_csr, cudaFuncAttributeMaxDynamicSharedMemorySize, NN * 4);

    const int din[6]  = {128, 256, 256, 512, 512, 256};
    const int dout[6] = {256, 256, 512, 512, 256, 256};
    const int woff[6] = {0, 32768, 98304, 229376, 491520, 622592};

    // 1) convert inputs + weights   2) CSR count+scan   3) CSR fill
    k_cvtall<<<dim3(1250, 13), 256>>>(x, wp);
    k_csr<<<1, 1024, NN * 4>>>(ei);
    k_fillcsr<<<(EE + 255) / 256, 256>>>(ei);

    const unsigned short* h = xb;
    for (int l = 0; l < 6; l++) {
        unsigned short* o = (l & 1) ? pB : pA;
        k_agg<<<(NN + 7) / 8, 256>>>(h, ag, din[l]);
        dim3 grid(dout[l] / 128, (NN + 127) / 128);
        if (l < 5)
            k_gemm_tc<true><<<grid, 256, SMEM_BYTES>>>(
                ag, h, wl + (size_t)woff[l] * 2, wr + (size_t)woff[l] * 2,
                blp[l], o, din[l], dout[l]);
        else
            k_gemm_tc<false><<<grid, 256, SMEM_BYTES>>>(
                ag, h, wl + (size_t)woff[l] * 2, wr + (size_t)woff[l] * 2,
                blp[l], o, din[l], dout[l]);
        h = o;
    }
    k_bounds<<<(NN + 255) / 256, 256>>>(batch);
    k_pool<<<GG, 256>>>(h);
    k_final<<<1, 384>>>(Wlin, blin, out);
}

// round 6
// speedup vs baseline: 1.2180x; 1.2180x over previous
#include <cuda_runtime.h>
#include <cuda_bf16.h>
#include <cstdint>

#define NN 20000
#define EE 160000
#define GG 64
#define MAXD 512
#define WTOT 688128

// ---------------- scratch (interleaved bf16 hi/lo planes) -------------------
// Layout per row: granule-pairs of [16B hi (8 elems) | 16B lo (8 elems)] along K.
__device__ __align__(16) unsigned short g_x[NN * 256];        // K=128
__device__ __align__(16) unsigned short g_ag[NN * MAXD * 2];
__device__ __align__(16) unsigned short g_pA[NN * MAXD * 2];
__device__ __align__(16) unsigned short g_pB[NN * MAXD * 2];
__device__ __align__(16) unsigned short g_wl[WTOT * 2];
__device__ __align__(16) unsigned short g_wr[WTOT * 2];
__device__ int   g_rowptr[NN + 1];
__device__ int   g_fill[NN];
__device__ int   g_csr[EE];
__device__ float g_pool[GG * 256];
__device__ int   g_gs[GG];
__device__ int   g_ge[GG];

__constant__ int c_din[6]  = {128, 256, 256, 512, 512, 256};
__constant__ int c_dout[6] = {256, 256, 512, 512, 256, 256};
__constant__ int c_woff[6] = {0, 32768, 98304, 229376, 491520, 622592};

struct WPtrs { const float* w[12]; };

// ---------------- helpers ----------------------------------------------------
__device__ __forceinline__ uint32_t smem_u32(const void* p) {
    uint32_t a;
    asm("{ .reg .u64 t; cvta.to.shared.u64 t, %1; cvt.u32.u64 %0, t; }" : "=r"(a) : "l"(p));
    return a;
}
__device__ __forceinline__ uint32_t pk2(float a, float b) {  // low16=a, high16=b
    uint32_t r;
    asm("cvt.rn.bf16x2.f32 %0, %1, %2;" : "=r"(r) : "f"(b), "f"(a));
    return r;
}
__device__ __forceinline__ void split2(float v0, float v1, uint32_t& hp, uint32_t& lp) {
    hp = pk2(v0, v1);
    float h0 = __uint_as_float(hp << 16);
    float h1 = __uint_as_float(hp & 0xFFFF0000u);
    lp = pk2(v0 - h0, v1 - h1);
}
__device__ __forceinline__ void ldm4(uint32_t* r, uint32_t a) {
    asm volatile("ldmatrix.sync.aligned.m8n8.x4.shared.b16 {%0,%1,%2,%3}, [%4];"
                 : "=r"(r[0]), "=r"(r[1]), "=r"(r[2]), "=r"(r[3]) : "r"(a));
}
#define MMA_BF16(c, a, b)                                                          \
    asm volatile("mma.sync.aligned.m16n8k16.row.col.f32.bf16.bf16.f32 "            \
        "{%0,%1,%2,%3}, {%4,%5,%6,%7}, {%8,%9}, {%0,%1,%2,%3};"                     \
        : "+f"((c)[0]), "+f"((c)[1]), "+f"((c)[2]), "+f"((c)[3])                    \
        : "r"((a)[0]), "r"((a)[1]), "r"((a)[2]), "r"((a)[3]),                       \
          "r"((b)[0]), "r"((b)[1]))
#define CP16(dst, src, sz)                                                         \
    asm volatile("cp.async.cg.shared.global [%0], [%1], 16, %2;"                    \
        :: "r"(dst), "l"(src), "r"(sz) : "memory")
#define CP_COMMIT() asm volatile("cp.async.commit_group;" ::: "memory")
#define CP_WAIT1()  asm volatile("cp.async.wait_group 1;" ::: "memory")

// ---------------- fused convert: x split + weight transpose/split -----------
__global__ void k_cvtall(const float* __restrict__ x, WPtrs wp) {
    int t = threadIdx.x;
    if (blockIdx.y == 0) {
        int gi = blockIdx.x * 256 + t;  // one granule-pair (8 elems)
        if (gi < NN * 16) {
            const float4* xs = (const float4*)(x + (size_t)gi * 8);
            float4 v0 = xs[0], v1 = xs[1];
            uint32_t h0, l0, h1, l1, h2, l2, h3, l3;
            split2(v0.x, v0.y, h0, l0); split2(v0.z, v0.w, h1, l1);
            split2(v1.x, v1.y, h2, l2); split2(v1.z, v1.w, h3, l3);
            uint4* dst = (uint4*)g_x + (size_t)gi * 2;
            dst[0] = make_uint4(h0, h1, h2, h3);
            dst[1] = make_uint4(l0, l1, l2, l3);
        }
    } else {
        int id = blockIdx.y - 1, li = id >> 1, lr = id & 1;
        int K = c_din[li], Ncol = c_dout[li];
        int i = blockIdx.x * 256 + t;
        if (i < K * Ncol) {
            int k = i / Ncol, n = i % Ncol;
            const float* W = wp.w[id];
            float v = W[i];
            uint32_t hp = pk2(v, v);
            float hf = __uint_as_float(hp << 16);
            uint32_t lp = pk2(v - hf, 0.f);
            unsigned short* dst = (lr ? g_wr : g_wl) + (size_t)c_woff[li] * 2;
            size_t o = (size_t)n * K * 2 + (size_t)(k >> 3) * 16 + (k & 7);
            dst[o]     = (unsigned short)(hp & 0xFFFFu);
            dst[o + 8] = (unsigned short)(lp & 0xFFFFu);
        }
    }
}

// ---------------- fused CSR count + scan (single block) ---------------------
__global__ void k_csr(const int* __restrict__ ei) {
    extern __shared__ int sdeg[];
    __shared__ int part[1024];
    int t = threadIdx.x;
    for (int i = t; i < NN; i += 1024) sdeg[i] = 0;
    if (t < GG) { g_gs[t] = NN; g_ge[t] = 0; }
    __syncthreads();
    for (int e = t; e < EE; e += 1024) atomicAdd(&sdeg[ei[EE + e]], 1);
    __syncthreads();
    const int CH = (NN + 1023) / 1024;
    int base = t * CH, s = 0;
    for (int i = 0; i < CH; i++) { int idx = base + i; if (idx < NN) s += sdeg[idx]; }
    part[t] = s;
    __syncthreads();
    for (int off = 1; off < 1024; off <<= 1) {
        int v = (t >= off) ? part[t - off] : 0;
        __syncthreads(); part[t] += v; __syncthreads();
    }
    int run = (t == 0) ? 0 : part[t - 1];
    for (int i = 0; i < CH; i++) {
        int idx = base + i;
        if (idx < NN) { int c = sdeg[idx]; g_rowptr[idx] = run; g_fill[idx] = run; run += c; }
    }
    if (t == 1023) g_rowptr[NN] = part[1023];
}
__global__ void k_fillcsr(const int* __restrict__ ei) {
    int e = blockIdx.x * blockDim.x + threadIdx.x;
    if (e < EE) { int d = ei[EE + e]; int p = atomicAdd(&g_fill[d], 1); g_csr[p] = ei[e]; }
}

// ---------------- mean aggregation: warp = (node, 128-feat chunk) -----------
#define UNPACK_ADD(a, v)                                                     \
    do {                                                                     \
        (a)[0] += __uint_as_float((v).x << 16);                              \
        (a)[1] += __uint_as_float((v).x & 0xFFFF0000u);                      \
        (a)[2] += __uint_as_float((v).y << 16);                              \
        (a)[3] += __uint_as_float((v).y & 0xFFFF0000u);                      \
        (a)[4] += __uint_as_float((v).z << 16);                              \
        (a)[5] += __uint_as_float((v).z & 0xFFFF0000u);                      \
        (a)[6] += __uint_as_float((v).w << 16);                              \
        (a)[7] += __uint_as_float((v).w & 0xFFFF0000u);                      \
    } while (0)

__global__ void k_agg(const unsigned short* __restrict__ in,
                      unsigned short* __restrict__ out, int K) {
    int node = blockIdx.x * 8 + (threadIdx.x >> 5);
    if (node >= NN) return;
    int lane = threadIdx.x & 31;
    int rs = K >> 2;  // uint4 per row
    int cidx = blockIdx.y * 32 + lane;
    int beg = g_rowptr[node], end = g_rowptr[node + 1];
    const uint4* base = (const uint4*)in;

    float a0[8], a1[8];
#pragma unroll
    for (int j = 0; j < 8; j++) { a0[j] = 0.f; a1[j] = 0.f; }

    int e = beg;
    for (; e + 2 <= end; e += 2) {
        int s0 = g_csr[e], s1 = g_csr[e + 1];
        uint4 v0 = base[(size_t)s0 * rs + cidx];
        uint4 v1 = base[(size_t)s1 * rs + cidx];
        UNPACK_ADD(a0, v0);
        UNPACK_ADD(a1, v1);
    }
    if (e < end) {
        uint4 v = base[(size_t)g_csr[e] * rs + cidx];
        UNPACK_ADD(a0, v);
    }

    int d = end - beg;
    float inv = 1.0f / (float)(d > 0 ? d : 1);
    bool isLo = lane & 1;
    float m[8];
#pragma unroll
    for (int j = 0; j < 8; j++) {
        float s = a0[j] + a1[j];
        m[j] = (s + __shfl_xor_sync(0xFFFFFFFFu, s, 1)) * inv;
    }
    uint32_t u[4];
#pragma unroll
    for (int j = 0; j < 4; j++) {
        uint32_t hp, lp;
        split2(m[2 * j], m[2 * j + 1], hp, lp);
        u[j] = isLo ? lp : hp;
    }
    ((uint4*)out)[(size_t)node * rs + cidx] = make_uint4(u[0], u[1], u[2], u[3]);
}

// ---------------- bf16 3x-split dual GEMM, 3-stage cp.async -----------------
#define T_A 0
#define T_B 16384
#define STAGE_B 32768
#define SMEM_BYTES 98304

template <bool LEAKY>
__global__ void __launch_bounds__(256) k_gemm_tc(
    const unsigned short* __restrict__ A1, const unsigned short* __restrict__ A2,
    const unsigned short* __restrict__ W1, const unsigned short* __restrict__ W2,
    const float* __restrict__ bias, unsigned short* __restrict__ O,
    int K, int DOUT)
{
    extern __shared__ char smem[];
    const uint32_t sb = smem_u32(smem);
    const int t = threadIdx.x, lane = t & 31, wid = t >> 5;
    const int wr = wid >> 2, wc = wid & 3;
    const int m0 = blockIdx.y * 128, n0 = blockIdx.x * 128;
    const int nc = K / 32, tot = 2 * nc;

    float acc[4][4][4];
#pragma unroll
    for (int i = 0; i < 4; i++)
#pragma unroll
        for (int j = 0; j < 4; j++)
#pragma unroll
            for (int k = 0; k < 4; k++) acc[i][j][k] = 0.f;

    // fill constants: thread -> (row = t>>1, granules gsel..gsel+3)
    const int frow = t >> 1;
    const uint32_t gsel = (uint32_t)(t & 1) * 4;
    const uint32_t rowb = (uint32_t)frow * 128;
    const uint32_t fswz = (uint32_t)(frow & 7) << 4;
    const int gra = m0 + frow;
    const uint32_t szA = (gra < NN) ? 16u : 0u;
    const size_t aoff = (size_t)(gra < NN ? gra : NN - 1) * K * 4;
    const size_t boff = (size_t)(n0 + frow) * K * 4;

    // MMA address constants
    const uint32_t lswz = (uint32_t)(lane & 7) << 4;
    const uint32_t arow = (uint32_t)(wr * 64 + (lane & 7) + ((lane >> 3) & 1) * 8);
    const uint32_t agr  = ((uint32_t)(lane >> 4)) * 32;
    const uint32_t brow = (uint32_t)(wc * 32 + (lane >> 4) * 8 + (lane & 7));
    const uint32_t bgr  = ((uint32_t)((lane >> 3) & 1)) * 32;

#define FILL(ch, stg) do {                                                         \
    const unsigned short *as_, *bs_; int kb_;                                      \
    if ((ch) < nc) { as_ = A1; bs_ = W1; kb_ = (ch) * 32; }                         \
    else           { as_ = A2; bs_ = W2; kb_ = ((ch) - nc) * 32; }                  \
    uint32_t sd_ = sb + (uint32_t)(stg) * STAGE_B + rowb;                           \
    const char* asrc = (const char*)as_ + aoff + (size_t)kb_ * 4;                   \
    const char* bsrc = (const char*)bs_ + boff + (size_t)kb_ * 4;                   \
    _Pragma("unroll")                                                               \
    for (int i_ = 0; i_ < 4; i_++) {                                                \
        uint32_t g_ = gsel + i_;                                                    \
        uint32_t off_ = (g_ * 16) ^ fswz;                                           \
        CP16(sd_ + T_A + off_, asrc + g_ * 16, szA);                                \
        CP16(sd_ + T_B + off_, bsrc + g_ * 16, 16u);                                \
    }                                                                               \
    CP_COMMIT();                                                                    \
} while (0)

    FILL(0, 0);
    FILL(1, 1);

    int stg = 0;
    for (int ch = 0; ch < tot; ch++) {
        CP_WAIT1();
        __syncthreads();
        if (ch + 2 < tot) {
            int ns = stg + 2; if (ns >= 3) ns -= 3;
            FILL(ch + 2, ns);
        } else {
            CP_COMMIT();
        }
        const uint32_t s0 = sb + (uint32_t)stg * STAGE_B;
#pragma unroll
        for (int ks = 0; ks < 2; ks++) {
            const uint32_t colb = (uint32_t)ks * 64;
            uint32_t bh[4][2], bl[4][2];
#pragma unroll
            for (int ntp = 0; ntp < 2; ntp++) {
                uint32_t rb_ = s0 + T_B + (brow + (uint32_t)ntp * 16) * 128;
                uint32_t rg[4];
                ldm4(rg, rb_ + ((colb + bgr) ^ lswz));
                bh[2 * ntp][0] = rg[0]; bh[2 * ntp][1] = rg[1];
                bh[2 * ntp + 1][0] = rg[2]; bh[2 * ntp + 1][1] = rg[3];
                ldm4(rg, rb_ + ((colb + 16 + bgr) ^ lswz));
                bl[2 * ntp][0] = rg[0]; bl[2 * ntp][1] = rg[1];
                bl[2 * ntp + 1][0] = rg[2]; bl[2 * ntp + 1][1] = rg[3];
            }
#pragma unroll
            for (int mt = 0; mt < 4; mt++) {
                uint32_t ab_ = s0 + T_A + (arow + (uint32_t)mt * 16) * 128;
                uint32_t ah[4], al[4];
                ldm4(ah, ab_ + ((colb + agr) ^ lswz));
                ldm4(al, ab_ + ((colb + 16 + agr) ^ lswz));
#pragma unroll
                for (int nt = 0; nt < 4; nt++) {
                    MMA_BF16(acc[mt][nt], ah, bh[nt]);
                    MMA_BF16(acc[mt][nt], ah, bl[nt]);
                    MMA_BF16(acc[mt][nt], al, bh[nt]);
                }
            }
        }
        stg++; if (stg >= 3) stg = 0;
    }
#undef FILL

    // epilogue: bias + optional leaky; interleaved hi/lo out
#pragma unroll
    for (int mt = 0; mt < 4; mt++) {
        int r0 = m0 + wr * 64 + mt * 16 + (lane >> 2);
        int r1 = r0 + 8;
#pragma unroll
        for (int nt = 0; nt < 4; nt++) {
            int c0 = n0 + wc * 32 + nt * 8 + (lane & 3) * 2;
            float2 b2 = *(const float2*)(bias + c0);
            float v0 = acc[mt][nt][0] + b2.x;
            float v1 = acc[mt][nt][1] + b2.y;
            float v2 = acc[mt][nt][2] + b2.x;
            float v3 = acc[mt][nt][3] + b2.y;
            if (LEAKY) {
                v0 = v0 >= 0.f ? v0 : 0.01f * v0;
                v1 = v1 >= 0.f ? v1 : 0.01f * v1;
                v2 = v2 >= 0.f ? v2 : 0.01f * v2;
                v3 = v3 >= 0.f ? v3 : 0.01f * v3;
            }
            size_t cb = (size_t)((c0 >> 3) * 32 + (c0 & 7) * 2);
            uint32_t hp, lp;
            if (r0 < NN) {
                char* p = (char*)O + (size_t)r0 * DOUT * 4 + cb;
                split2(v0, v1, hp, lp);
                *(uint32_t*)p = hp;
                *(uint32_t*)(p + 16) = lp;
            }
            if (r1 < NN) {
                char* p = (char*)O + (size_t)r1 * DOUT * 4 + cb;
                split2(v2, v3, hp, lp);
                *(uint32_t*)p = hp;
                *(uint32_t*)(p + 16) = lp;
            }
        }
    }
}

// ---------------- pool + head ------------------------------------------------
__global__ void k_bounds(const int* __restrict__ batch) {
    int n = blockIdx.x * blockDim.x + threadIdx.x;
    if (n < NN) {
        int b = batch[n];
        atomicMin(&g_gs[b], n);
        atomicMax(&g_ge[b], n + 1);
    }
}
__global__ void k_pool(const unsigned short* __restrict__ H) {
    int g = blockIdx.x, f = threadIdx.x;
    int s = g_gs[g], e = g_ge[g];
    size_t off = (size_t)(f >> 3) * 16 + (f & 7);
    float sum = 0.f;
    for (int n = s; n < e; n++) {
        const unsigned short* row = H + (size_t)n * 512;
        sum += __uint_as_float(((uint32_t)row[off]) << 16)
             + __uint_as_float(((uint32_t)row[off + 8]) << 16);
    }
    int c = e - s; if (c < 1) c = 1;
    g_pool[g * 256 + f] = sum / (float)c;
}
__global__ void k_final(const float* __restrict__ Wlin, const float* __restrict__ blin,
                        float* __restrict__ out) {
    int idx = threadIdx.x;
    if (idx >= GG * 6) return;
    int g = idx / 6, o = idx % 6;
    float s = blin[o];
#pragma unroll 8
    for (int k = 0; k < 256; k++) s += g_pool[g * 256 + k] * Wlin[k * 6 + o];
    out[idx] = s;
}

// ---------------- launcher ----------------------------------------------------
extern "C" void kernel_launch(void* const* d_in, const int* in_sizes, int n_in,
                              void* d_out, int out_size) {
    const float* x     = (const float*)d_in[0];
    const int*   ei    = (const int*)d_in[1];
    const int*   batch = (const int*)d_in[2];
    WPtrs wp;
    const float* blp[6];
    for (int l = 0; l < 6; l++) {
        wp.w[2 * l]     = (const float*)d_in[3 + 3 * l];  // Wl
        blp[l]          = (const float*)d_in[4 + 3 * l];
        wp.w[2 * l + 1] = (const float*)d_in[5 + 3 * l];  // Wr
    }
    const float* Wlin = (const float*)d_in[21];
    const float* blin = (const float*)d_in[22];
    float* out = (float*)d_out;

    unsigned short *xb, *ag, *pA, *pB, *wl, *wr;
    cudaGetSymbolAddress((void**)&xb, g_x);
    cudaGetSymbolAddress((void**)&ag, g_ag);
    cudaGetSymbolAddress((void**)&pA, g_pA);
    cudaGetSymbolAddress((void**)&pB, g_pB);
    cudaGetSymbolAddress((void**)&wl, g_wl);
    cudaGetSymbolAddress((void**)&wr, g_wr);

    cudaFuncSetAttribute(k_gemm_tc<true>,  cudaFuncAttributeMaxDynamicSharedMemorySize, SMEM_BYTES);
    cudaFuncSetAttribute(k_gemm_tc<false>, cudaFuncAttributeMaxDynamicSharedMemorySize, SMEM_BYTES);
    cudaFuncSetAttribute(k_csr, cudaFuncAttributeMaxDynamicSharedMemorySize, NN * 4);

    const int din[6]  = {128, 256, 256, 512, 512, 256};
    const int dout[6] = {256, 256, 512, 512, 256, 256};
    const int woff[6] = {0, 32768, 98304, 229376, 491520, 622592};

    // 1) convert inputs + weights   2) CSR count+scan   3) CSR fill
    k_cvtall<<<dim3(1250, 13), 256>>>(x, wp);
    k_csr<<<1, 1024, NN * 4>>>(ei);
    k_fillcsr<<<(EE + 255) / 256, 256>>>(ei);

    const unsigned short* h = xb;
    for (int l = 0; l < 6; l++) {
        unsigned short* o = (l & 1) ? pB : pA;
        dim3 agrid((NN + 7) / 8, din[l] >> 7);
        k_agg<<<agrid, 256>>>(h, ag, din[l]);
        dim3 grid(dout[l] / 128, (NN + 127) / 128);
        if (l < 5)
            k_gemm_tc<true><<<grid, 256, SMEM_BYTES>>>(
                ag, h, wl + (size_t)woff[l] * 2, wr + (size_t)woff[l] * 2,
                blp[l], o, din[l], dout[l]);
        else
            k_gemm_tc<false><<<grid, 256, SMEM_BYTES>>>(
                ag, h, wl + (size_t)woff[l] * 2, wr + (size_t)woff[l] * 2,
                blp[l], o, din[l], dout[l]);
        h = o;
    }
    k_bounds<<<(NN + 255) / 256, 256>>>(batch);
    k_pool<<<GG, 256>>>(h);
    k_final<<<1, 384>>>(Wlin, blin, out);
}